// round 7
// baseline (speedup 1.0000x reference)
#include <cuda_runtime.h>
#include <cuda_bf16.h>
#include <math.h>
#include <stdint.h>

#define EPS        1e-6f
#define K_COMM     64
#define O_DIM      1024
#define M_TILE     128
#define O_STAGE    64
#define AS_STRIDE  72     // bf16 elements per smem row (padded: conflict-free ldmatrix-free frags)
#define LS_STRIDE  65     // fp32 logits row stride (conflict-free column sweeps)

// Scratch (no allocations allowed): bf16 log-weights + per-tile partial sums.
__device__ __nv_bfloat16 g_logw[K_COMM * O_DIM];
__device__ float         g_partials[1024];

__global__ void prep_logw(const float* __restrict__ otu) {
    int i = blockIdx.x * blockDim.x + threadIdx.x;
    if (i < K_COMM * O_DIM)
        g_logw[i] = __float2bfloat16(logf(otu[i] + EPS));
}

__device__ __forceinline__ uint32_t pack2(float a, float b) {
    __nv_bfloat162 h = __floats2bfloat162_rn(a, b);
    return *reinterpret_cast<uint32_t*>(&h);
}

__device__ __forceinline__ void mma16816(float c[4], const uint32_t a[4], const uint32_t b[2]) {
    asm volatile(
        "mma.sync.aligned.m16n8k16.row.col.f32.bf16.bf16.f32 "
        "{%0,%1,%2,%3}, {%4,%5,%6,%7}, {%8,%9}, {%0,%1,%2,%3};\n"
        : "+f"(c[0]), "+f"(c[1]), "+f"(c[2]), "+f"(c[3])
        : "r"(a[0]), "r"(a[1]), "r"(a[2]), "r"(a[3]),
          "r"(b[0]), "r"(b[1]));
}

// One CTA = 128 rows of counts. 8 warps: warpM in 0..3 (32 rows each), warpN in 0..1 (32 communities).
// Stages O in chunks of 64: counts fp32 -> bf16 into smem, weights bf16 from L2-resident g_logw.
// Fused epilogue: logits -> smem, per-row max-subtracted logsumexp, block-sum -> g_partials.
__global__ __launch_bounds__(256) void gemm_lse(const float* __restrict__ counts,
                                                const float* __restrict__ comm,
                                                int nRows) {
    __shared__ __align__(16) unsigned char smem_raw[M_TILE * LS_STRIDE * 4]; // 33280 B >= As+Bs (27648 B)
    __shared__ float s_prior[K_COMM];
    __shared__ float s_red[256];

    __nv_bfloat16* As = reinterpret_cast<__nv_bfloat16*>(smem_raw);
    __nv_bfloat16* Bs = As + M_TILE * AS_STRIDE;          // byte offset 18432 (16B aligned)
    float*         Ls = reinterpret_cast<float*>(smem_raw); // reused after GEMM

    const int tid     = threadIdx.x;
    const int lane    = tid & 31;
    const int warp    = tid >> 5;
    const int warpM   = warp >> 1;   // 0..3
    const int warpN   = warp & 1;    // 0..1
    const int groupID = lane >> 2;   // 0..7
    const int tig     = lane & 3;    // 0..3

    if (tid < K_COMM) s_prior[tid] = logf(comm[tid] + EPS);

    const int rowBase = blockIdx.x * M_TILE;

    float acc[2][4][4];
#pragma unroll
    for (int mt = 0; mt < 2; ++mt)
#pragma unroll
        for (int nt = 0; nt < 4; ++nt)
#pragma unroll
            for (int i = 0; i < 4; ++i) acc[mt][nt][i] = 0.f;

    // counts-load role: thread t -> row t/2, half t&1 (32 floats = 2x float4 strip)
    const int r    = tid >> 1;
    const int half = tid & 1;
    const int gr   = rowBase + r;
    const bool rowValid = (gr < nRows);
    // weight-load role: thread t -> k row t/4, quarter t&3 (16 bf16 = 2x uint4)
    const int kk = tid >> 2;
    const int q  = tid & 3;

    for (int s = 0; s < O_DIM / O_STAGE; ++s) {
        const int oBase = s * O_STAGE;

        // ---- stage counts tile (fp32 -> bf16) ----
        uint32_t* dstA = reinterpret_cast<uint32_t*>(As + r * AS_STRIDE + half * 32);
        if (rowValid) {
            const float4* src = reinterpret_cast<const float4*>(
                counts + (size_t)gr * O_DIM + oBase + half * 32);
#pragma unroll
            for (int i = 0; i < 8; ++i) {
                float4 v = src[i];
                dstA[2 * i]     = pack2(v.x, v.y);
                dstA[2 * i + 1] = pack2(v.z, v.w);
            }
        } else {
#pragma unroll
            for (int i = 0; i < 16; ++i) dstA[i] = 0u;
        }

        // ---- stage weights tile (bf16, L2-resident) ----
        {
            const uint4* wsrc = reinterpret_cast<const uint4*>(g_logw + kk * O_DIM + oBase + q * 16);
            uint32_t* dstB = reinterpret_cast<uint32_t*>(Bs + kk * AS_STRIDE + q * 16);
            uint4 w0 = wsrc[0];
            uint4 w1 = wsrc[1];
            dstB[0] = w0.x; dstB[1] = w0.y; dstB[2] = w0.z; dstB[3] = w0.w;
            dstB[4] = w1.x; dstB[5] = w1.y; dstB[6] = w1.z; dstB[7] = w1.w;
        }
        __syncthreads();

        // ---- MMA over this stage: 4 k-chunks of 16 ----
#pragma unroll
        for (int oc = 0; oc < O_STAGE; oc += 16) {
            uint32_t a[2][4];
#pragma unroll
            for (int mt = 0; mt < 2; ++mt) {
                const int row0 = warpM * 32 + mt * 16 + groupID;
                const __nv_bfloat16* p = As + row0 * AS_STRIDE + oc + 2 * tig;
                a[mt][0] = *reinterpret_cast<const uint32_t*>(p);
                a[mt][1] = *reinterpret_cast<const uint32_t*>(p + 8 * AS_STRIDE);
                a[mt][2] = *reinterpret_cast<const uint32_t*>(p + 8);
                a[mt][3] = *reinterpret_cast<const uint32_t*>(p + 8 * AS_STRIDE + 8);
            }
            uint32_t b[4][2];
#pragma unroll
            for (int nt = 0; nt < 4; ++nt) {
                const int k0 = warpN * 32 + nt * 8 + groupID;
                const __nv_bfloat16* p = Bs + k0 * AS_STRIDE + oc + 2 * tig;
                b[nt][0] = *reinterpret_cast<const uint32_t*>(p);
                b[nt][1] = *reinterpret_cast<const uint32_t*>(p + 8);
            }
#pragma unroll
            for (int mt = 0; mt < 2; ++mt)
#pragma unroll
                for (int nt = 0; nt < 4; ++nt)
                    mma16816(acc[mt][nt], a[mt], b[nt]);
        }
        __syncthreads();
    }

    // ---- spill logits to smem (C-frag layout -> row-major [128][64], stride 65) ----
#pragma unroll
    for (int mt = 0; mt < 2; ++mt) {
        const int r0 = warpM * 32 + mt * 16 + groupID;
#pragma unroll
        for (int nt = 0; nt < 4; ++nt) {
            const int c0 = warpN * 32 + nt * 8 + 2 * tig;
            Ls[r0 * LS_STRIDE + c0]           = acc[mt][nt][0];
            Ls[r0 * LS_STRIDE + c0 + 1]       = acc[mt][nt][1];
            Ls[(r0 + 8) * LS_STRIDE + c0]     = acc[mt][nt][2];
            Ls[(r0 + 8) * LS_STRIDE + c0 + 1] = acc[mt][nt][3];
        }
    }
    __syncthreads();

    // ---- per-row logsumexp (threads 0..127 each own one row) ----
    float val = 0.f;
    if (tid < M_TILE) {
        const int grr = rowBase + tid;
        if (grr < nRows) {
            float m = -INFINITY;
#pragma unroll
            for (int k = 0; k < K_COMM; ++k) {
                float x = Ls[tid * LS_STRIDE + k] + s_prior[k];
                Ls[tid * LS_STRIDE + k] = x;
                m = fmaxf(m, x);
            }
            float ssum = 0.f;
#pragma unroll
            for (int k = 0; k < K_COMM; ++k)
                ssum += expf(Ls[tid * LS_STRIDE + k] - m);
            val = m + logf(ssum);
        }
    }
    s_red[tid] = val;
    __syncthreads();
#pragma unroll
    for (int off = 128; off > 0; off >>= 1) {
        if (tid < off) s_red[tid] += s_red[tid + off];
        __syncthreads();
    }
    if (tid == 0) g_partials[blockIdx.x] = s_red[0];
}

__global__ void final_reduce(float* __restrict__ out, int nTiles) {
    __shared__ double sred[256];
    double s = 0.0;
    for (int i = threadIdx.x; i < nTiles; i += 256) s += (double)g_partials[i];
    sred[threadIdx.x] = s;
    __syncthreads();
#pragma unroll
    for (int off = 128; off > 0; off >>= 1) {
        if (threadIdx.x < off) sred[threadIdx.x] += sred[threadIdx.x + off];
        __syncthreads();
    }
    if (threadIdx.x == 0) out[0] = (float)sred[0];
}

extern "C" void kernel_launch(void* const* d_in, const int* in_sizes, int n_in,
                              void* d_out, int out_size) {
    const float* counts = (const float*)d_in[0];   // (N, 1024) fp32
    const float* otu    = (const float*)d_in[1];   // (64, 1024) fp32
    const float* comm   = (const float*)d_in[2];   // (64,) fp32
    float* out = (float*)d_out;                    // scalar fp32

    const int nRows  = in_sizes[0] / O_DIM;
    const int nTiles = (nRows + M_TILE - 1) / M_TILE;

    prep_logw<<<(K_COMM * O_DIM + 255) / 256, 256>>>(otu);
    gemm_lse<<<nTiles, 256>>>(counts, comm, nRows);
    final_reduce<<<1, 256>>>(out, nTiles);
}

// round 8
// speedup vs baseline: 1.0051x; 1.0051x over previous
#include <cuda_runtime.h>
#include <cuda_bf16.h>
#include <math.h>
#include <stdint.h>

#define EPS        1e-6f
#define K_COMM     64
#define O_DIM      1024
#define M_TILE     128
#define O_STAGE    64
#define AS_STRIDE  72     // bf16 elements per smem row (padded: conflict-free ldmatrix-free frags)
#define LS_STRIDE  65     // fp32 logits row stride (conflict-free column sweeps)

// Scratch (no allocations allowed): bf16 log-weights + per-tile partial sums.
__device__ __nv_bfloat16 g_logw[K_COMM * O_DIM];
__device__ float         g_partials[1024];

__global__ void prep_logw(const float* __restrict__ otu) {
    int i = blockIdx.x * blockDim.x + threadIdx.x;
    if (i < K_COMM * O_DIM)
        g_logw[i] = __float2bfloat16(logf(otu[i] + EPS));
}

__device__ __forceinline__ uint32_t pack2(float a, float b) {
    __nv_bfloat162 h = __floats2bfloat162_rn(a, b);
    return *reinterpret_cast<uint32_t*>(&h);
}

__device__ __forceinline__ void mma16816(float c[4], const uint32_t a[4], const uint32_t b[2]) {
    asm volatile(
        "mma.sync.aligned.m16n8k16.row.col.f32.bf16.bf16.f32 "
        "{%0,%1,%2,%3}, {%4,%5,%6,%7}, {%8,%9}, {%0,%1,%2,%3};\n"
        : "+f"(c[0]), "+f"(c[1]), "+f"(c[2]), "+f"(c[3])
        : "r"(a[0]), "r"(a[1]), "r"(a[2]), "r"(a[3]),
          "r"(b[0]), "r"(b[1]));
}

// One CTA = 128 rows of counts. 8 warps: warpM in 0..3 (32 rows each), warpN in 0..1 (32 communities).
// Stages O in chunks of 64: counts fp32 -> bf16 into smem, weights bf16 from L2-resident g_logw.
// Fused epilogue: logits -> smem, per-row max-subtracted logsumexp, block-sum -> g_partials.
__global__ __launch_bounds__(256) void gemm_lse(const float* __restrict__ counts,
                                                const float* __restrict__ comm,
                                                int nRows) {
    __shared__ __align__(16) unsigned char smem_raw[M_TILE * LS_STRIDE * 4]; // 33280 B >= As+Bs (27648 B)
    __shared__ float s_prior[K_COMM];
    __shared__ float s_red[256];

    __nv_bfloat16* As = reinterpret_cast<__nv_bfloat16*>(smem_raw);
    __nv_bfloat16* Bs = As + M_TILE * AS_STRIDE;          // byte offset 18432 (16B aligned)
    float*         Ls = reinterpret_cast<float*>(smem_raw); // reused after GEMM

    const int tid     = threadIdx.x;
    const int lane    = tid & 31;
    const int warp    = tid >> 5;
    const int warpM   = warp >> 1;   // 0..3
    const int warpN   = warp & 1;    // 0..1
    const int groupID = lane >> 2;   // 0..7
    const int tig     = lane & 3;    // 0..3

    if (tid < K_COMM) s_prior[tid] = logf(comm[tid] + EPS);

    const int rowBase = blockIdx.x * M_TILE;

    float acc[2][4][4];
#pragma unroll
    for (int mt = 0; mt < 2; ++mt)
#pragma unroll
        for (int nt = 0; nt < 4; ++nt)
#pragma unroll
            for (int i = 0; i < 4; ++i) acc[mt][nt][i] = 0.f;

    // counts-load role: thread t -> row t/2, half t&1 (32 floats = 2x float4 strip)
    const int r    = tid >> 1;
    const int half = tid & 1;
    const int gr   = rowBase + r;
    const bool rowValid = (gr < nRows);
    // weight-load role: thread t -> k row t/4, quarter t&3 (16 bf16 = 2x uint4)
    const int kk = tid >> 2;
    const int q  = tid & 3;

    for (int s = 0; s < O_DIM / O_STAGE; ++s) {
        const int oBase = s * O_STAGE;

        // ---- stage counts tile (fp32 -> bf16) ----
        uint32_t* dstA = reinterpret_cast<uint32_t*>(As + r * AS_STRIDE + half * 32);
        if (rowValid) {
            const float4* src = reinterpret_cast<const float4*>(
                counts + (size_t)gr * O_DIM + oBase + half * 32);
#pragma unroll
            for (int i = 0; i < 8; ++i) {
                float4 v = src[i];
                dstA[2 * i]     = pack2(v.x, v.y);
                dstA[2 * i + 1] = pack2(v.z, v.w);
            }
        } else {
#pragma unroll
            for (int i = 0; i < 16; ++i) dstA[i] = 0u;
        }

        // ---- stage weights tile (bf16, L2-resident) ----
        {
            const uint4* wsrc = reinterpret_cast<const uint4*>(g_logw + kk * O_DIM + oBase + q * 16);
            uint32_t* dstB = reinterpret_cast<uint32_t*>(Bs + kk * AS_STRIDE + q * 16);
            uint4 w0 = wsrc[0];
            uint4 w1 = wsrc[1];
            dstB[0] = w0.x; dstB[1] = w0.y; dstB[2] = w0.z; dstB[3] = w0.w;
            dstB[4] = w1.x; dstB[5] = w1.y; dstB[6] = w1.z; dstB[7] = w1.w;
        }
        __syncthreads();

        // ---- MMA over this stage: 4 k-chunks of 16 ----
#pragma unroll
        for (int oc = 0; oc < O_STAGE; oc += 16) {
            uint32_t a[2][4];
#pragma unroll
            for (int mt = 0; mt < 2; ++mt) {
                const int row0 = warpM * 32 + mt * 16 + groupID;
                const __nv_bfloat16* p = As + row0 * AS_STRIDE + oc + 2 * tig;
                a[mt][0] = *reinterpret_cast<const uint32_t*>(p);
                a[mt][1] = *reinterpret_cast<const uint32_t*>(p + 8 * AS_STRIDE);
                a[mt][2] = *reinterpret_cast<const uint32_t*>(p + 8);
                a[mt][3] = *reinterpret_cast<const uint32_t*>(p + 8 * AS_STRIDE + 8);
            }
            uint32_t b[4][2];
#pragma unroll
            for (int nt = 0; nt < 4; ++nt) {
                const int k0 = warpN * 32 + nt * 8 + groupID;
                const __nv_bfloat16* p = Bs + k0 * AS_STRIDE + oc + 2 * tig;
                b[nt][0] = *reinterpret_cast<const uint32_t*>(p);
                b[nt][1] = *reinterpret_cast<const uint32_t*>(p + 8);
            }
#pragma unroll
            for (int mt = 0; mt < 2; ++mt)
#pragma unroll
                for (int nt = 0; nt < 4; ++nt)
                    mma16816(acc[mt][nt], a[mt], b[nt]);
        }
        __syncthreads();
    }

    // ---- spill logits to smem (C-frag layout -> row-major [128][64], stride 65) ----
#pragma unroll
    for (int mt = 0; mt < 2; ++mt) {
        const int r0 = warpM * 32 + mt * 16 + groupID;
#pragma unroll
        for (int nt = 0; nt < 4; ++nt) {
            const int c0 = warpN * 32 + nt * 8 + 2 * tig;
            Ls[r0 * LS_STRIDE + c0]           = acc[mt][nt][0];
            Ls[r0 * LS_STRIDE + c0 + 1]       = acc[mt][nt][1];
            Ls[(r0 + 8) * LS_STRIDE + c0]     = acc[mt][nt][2];
            Ls[(r0 + 8) * LS_STRIDE + c0 + 1] = acc[mt][nt][3];
        }
    }
    __syncthreads();

    // ---- per-row logsumexp (threads 0..127 each own one row) ----
    float val = 0.f;
    if (tid < M_TILE) {
        const int grr = rowBase + tid;
        if (grr < nRows) {
            float m = -INFINITY;
#pragma unroll
            for (int k = 0; k < K_COMM; ++k) {
                float x = Ls[tid * LS_STRIDE + k] + s_prior[k];
                Ls[tid * LS_STRIDE + k] = x;
                m = fmaxf(m, x);
            }
            float ssum = 0.f;
#pragma unroll
            for (int k = 0; k < K_COMM; ++k)
                ssum += expf(Ls[tid * LS_STRIDE + k] - m);
            val = m + logf(ssum);
        }
    }
    s_red[tid] = val;
    __syncthreads();
#pragma unroll
    for (int off = 128; off > 0; off >>= 1) {
        if (tid < off) s_red[tid] += s_red[tid + off];
        __syncthreads();
    }
    if (tid == 0) g_partials[blockIdx.x] = s_red[0];
}

__global__ void final_reduce(float* __restrict__ out, int nTiles) {
    __shared__ double sred[256];
    double s = 0.0;
    for (int i = threadIdx.x; i < nTiles; i += 256) s += (double)g_partials[i];
    sred[threadIdx.x] = s;
    __syncthreads();
#pragma unroll
    for (int off = 128; off > 0; off >>= 1) {
        if (threadIdx.x < off) sred[threadIdx.x] += sred[threadIdx.x + off];
        __syncthreads();
    }
    if (threadIdx.x == 0) out[0] = (float)sred[0];
}

extern "C" void kernel_launch(void* const* d_in, const int* in_sizes, int n_in,
                              void* d_out, int out_size) {
    const float* counts = (const float*)d_in[0];   // (N, 1024) fp32
    const float* otu    = (const float*)d_in[1];   // (64, 1024) fp32
    const float* comm   = (const float*)d_in[2];   // (64,) fp32
    float* out = (float*)d_out;                    // scalar fp32

    const int nRows  = in_sizes[0] / O_DIM;
    const int nTiles = (nRows + M_TILE - 1) / M_TILE;

    prep_logw<<<(K_COMM * O_DIM + 255) / 256, 256>>>(otu);
    gemm_lse<<<nTiles, 256>>>(counts, comm, nRows);
    final_reduce<<<1, 256>>>(out, nTiles);
}